// round 5
// baseline (speedup 1.0000x reference)
#include <cuda_runtime.h>
#include <math.h>
#include <stdint.h>

#define N_NODES 50000
#define N_EDGES 150000
#define HDIM    512
#define HIDDIM  64
#define NGRAPH  64

// ---------------- scratch (device globals; no allocation allowed) ----------------
__device__ float  g_X  [(size_t)N_NODES * HDIM];
__device__ float  g_Hb [(size_t)N_NODES * HDIM];
__device__ float  g_AGG[(size_t)N_NODES * HDIM];
__device__ float  g_Y1 [(size_t)N_NODES * HIDDIM];
__device__ float  g_mask[N_NODES];
__device__ float  g_inv [N_NODES];
__device__ float  g_sA  [N_NODES];   // scalar agg buffer (mask propagate)
__device__ float  g_sB  [N_NODES];   // scalar agg buffer (conv1 agg, later y2)
__device__ float  g_cnt [NGRAPH];
__device__ float  g_bmax[NGRAPH];
__device__ float  g_bmin[NGRAPH];
__device__ double g_dsum[HDIM];
__device__ double g_dsq [HDIM];
__device__ float  g_bnA [HDIM];
__device__ float  g_bnB [HDIM];

__device__ __forceinline__ float* bufp(int b) {
    switch (b) {
        case 0: return g_X;
        case 1: return g_Hb;
        case 2: return g_AGG;
        default: return g_Y1;
    }
}

__device__ __forceinline__ float lrelu(float v) { return v > 0.f ? v : 0.01f * v; }

__device__ __forceinline__ void atomicMaxFloat(float* addr, float v) {
    if (v >= 0.f) atomicMax((int*)addr, __float_as_int(v));
    else          atomicMin((unsigned int*)addr, __float_as_uint(v));
}
__device__ __forceinline__ void atomicMinFloat(float* addr, float v) {
    if (v >= 0.f) atomicMin((int*)addr, __float_as_int(v));
    else          atomicMax((unsigned int*)addr, __float_as_uint(v));
}

// ---------------- small setup kernels ----------------
__global__ void k_setup() {
    int t = threadIdx.x;
    if (t < NGRAPH) {
        g_cnt[t]  = 0.f;
        g_bmax[t] = __int_as_float(0xff800000);  // -inf
        g_bmin[t] = __int_as_float(0x7f800000);  // +inf
    }
}

__global__ void k_count(const int* __restrict__ batch) {
    int i = blockIdx.x * blockDim.x + threadIdx.x;
    if (i < N_NODES) atomicAdd(&g_cnt[batch[i]], 1.0f);
}

__global__ void k_prep(const float* __restrict__ x, const int* __restrict__ batch) {
    int i = blockIdx.x * blockDim.x + threadIdx.x;
    if (i < N_NODES) {
        g_inv[i]  = rsqrtf(g_cnt[batch[i]]);
        g_mask[i] = (fabsf(x[i]) > 0.f) ? 1.f : 0.f;
        g_sA[i] = 0.f;
        g_sB[i] = 0.f;
    }
}

__global__ void k_edge_mask(const int* __restrict__ src, const int* __restrict__ dst) {
    int e = blockIdx.x * blockDim.x + threadIdx.x;
    if (e < N_EDGES) atomicAdd(&g_sA[dst[e]], g_mask[src[e]]);
}

__global__ void k_mask_update() {
    int i = blockIdx.x * blockDim.x + threadIdx.x;
    if (i < N_NODES) {
        g_mask[i] = (g_mask[i] + g_sA[i] > 0.f) ? 1.f : 0.f;
        g_sA[i] = 0.f;  // ready for next propagate
    }
}

__global__ void k_edge_x(const int* __restrict__ src, const int* __restrict__ dst,
                         const float* __restrict__ x) {
    int e = blockIdx.x * blockDim.x + threadIdx.x;
    if (e < N_EDGES) atomicAdd(&g_sB[dst[e]], x[src[e]]);
}

// h1 = relu(((1+eps)*x + agg) * w1[j] + b1[j])   (input dim 1)
__global__ void k_conv1_h1(const float* __restrict__ x, const float* __restrict__ w1,
                           const float* __restrict__ b1, const float* __restrict__ eps) {
    size_t idx = (size_t)blockIdx.x * blockDim.x + threadIdx.x;
    if (idx >= (size_t)N_NODES * HDIM) return;
    int i = (int)(idx >> 9);
    int j = (int)(idx & 511);
    float h0 = (1.f + eps[0]) * x[i] + g_sB[i];
    float v = fmaf(h0, w1[j], b1[j]);
    g_Hb[idx] = fmaxf(v, 0.f);
}

// ---------------- SGEMM: C = epi(A @ W + bias) ----------------
// A: MxK row-major (device buf), W: KxN row-major (input), C: MxN (device buf)
// mode 0: relu   mode 1: leaky * mask[row]
#define BM 128
#define BN 128
#define BK 8
#define TM 8
#define TN 8
__global__ __launch_bounds__(256, 2)
void k_sgemm(int Abuf, const float* __restrict__ W, const float* __restrict__ bias,
             int Cbuf, int M, int K, int Nd, int mode) {
    const float* A = bufp(Abuf);
    float* C = bufp(Cbuf);

    __shared__ float As[BK][BM];
    __shared__ float Bs[BK][BN];

    int tid  = threadIdx.x;
    int row0 = blockIdx.y * BM;
    int col0 = blockIdx.x * BN;

    int trow = (tid >> 4) * TM;   // 0..120
    int tcol = (tid & 15) * TN;   // 0..120

    int lrowA = tid >> 1;            // 0..127
    int lcolA = (tid & 1) * 4;       // 0 or 4
    int lrowB = tid >> 5;            // 0..7
    int lcolB = (tid & 31) * 4;      // 0..124

    float acc[TM][TN];
#pragma unroll
    for (int i = 0; i < TM; i++)
#pragma unroll
        for (int j = 0; j < TN; j++) acc[i][j] = 0.f;

    int arow = row0 + lrowA;
    bool aval = arow < M;
    int bcol = col0 + lcolB;
    bool bval = bcol < Nd;

    for (int kt = 0; kt < K; kt += BK) {
        float4 av = make_float4(0.f, 0.f, 0.f, 0.f);
        if (aval) av = *(const float4*)(A + (size_t)arow * K + kt + lcolA);
        As[lcolA + 0][lrowA] = av.x;
        As[lcolA + 1][lrowA] = av.y;
        As[lcolA + 2][lrowA] = av.z;
        As[lcolA + 3][lrowA] = av.w;

        float4 bv = make_float4(0.f, 0.f, 0.f, 0.f);
        if (bval) bv = *(const float4*)(W + (size_t)(kt + lrowB) * Nd + bcol);
        *(float4*)&Bs[lrowB][lcolB] = bv;

        __syncthreads();
#pragma unroll
        for (int k = 0; k < BK; k++) {
            float a[TM], b[TN];
            *(float4*)&a[0] = *(float4*)&As[k][trow];
            *(float4*)&a[4] = *(float4*)&As[k][trow + 4];
            *(float4*)&b[0] = *(float4*)&Bs[k][tcol];
            *(float4*)&b[4] = *(float4*)&Bs[k][tcol + 4];
#pragma unroll
            for (int i = 0; i < TM; i++)
#pragma unroll
                for (int j = 0; j < TN; j++) acc[i][j] = fmaf(a[i], b[j], acc[i][j]);
        }
        __syncthreads();
    }

#pragma unroll
    for (int i = 0; i < TM; i++) {
        int r = row0 + trow + i;
        if (r >= M) continue;
        float mi = (mode == 1) ? g_mask[r] : 1.f;
#pragma unroll
        for (int j = 0; j < TN; j++) {
            int c = col0 + tcol + j;
            if (c >= Nd) continue;
            float v = acc[i][j] + bias[c];
            if (mode == 0) v = fmaxf(v, 0.f);
            else           v = lrelu(v) * mi;
            C[(size_t)r * Nd + c] = v;
        }
    }
}

// ---------------- BN helpers ----------------
__global__ void k_zstat() {
    int t = threadIdx.x;
    g_dsum[t] = 0.0;
    g_dsq[t]  = 0.0;
}

#define BN_ROWS 256
__global__ void k_bn_reduce(int buf, int M) {
    const float* X = bufp(buf);
    int col = threadIdx.x;  // 512
    int r0  = blockIdx.x * BN_ROWS;
    int r1  = min(r0 + BN_ROWS, M);
    float s = 0.f, q = 0.f;
    for (int r = r0; r < r1; r++) {
        float v = X[(size_t)r * HDIM + col];
        s += v;
        q = fmaf(v, v, q);
    }
    atomicAdd(&g_dsum[col], (double)s);
    atomicAdd(&g_dsq[col], (double)q);
}

__global__ void k_bn_final(const float* __restrict__ gam, const float* __restrict__ bet, int M) {
    int j = threadIdx.x;
    double mu  = g_dsum[j] / (double)M;
    double var = g_dsq[j] / (double)M - mu * mu;
    float  rs  = rsqrtf(fmaxf((float)var, 0.f) + 1e-5f);
    float  a   = gam[j] * rs;
    g_bnA[j] = a;
    g_bnB[j] = bet[j] - a * (float)mu;
}

// X = leaky(bn(H2)) * mask * inv      (conv1 epilogue; H2 in g_AGG)
__global__ void k_apply_conv1() {
    size_t idx = (size_t)blockIdx.x * blockDim.x + threadIdx.x;
    if (idx >= (size_t)N_NODES * HDIM) return;
    int i = (int)(idx >> 9);
    int j = (int)(idx & 511);
    float v = lrelu(fmaf(g_AGG[idx], g_bnA[j], g_bnB[j]));
    g_X[idx] = v * g_mask[i] * g_inv[i];
}

// X = (X + leaky(bn(H2))) * mask * inv  (mid-layer epilogue; H2 in g_AGG)
__global__ void k_apply_mid() {
    size_t idx = (size_t)blockIdx.x * blockDim.x + threadIdx.x;
    if (idx >= (size_t)N_NODES * HDIM) return;
    int i = (int)(idx >> 9);
    int j = (int)(idx & 511);
    float t = lrelu(fmaf(g_AGG[idx], g_bnA[j], g_bnB[j]));
    g_X[idx] = (g_X[idx] + t) * g_mask[i] * g_inv[i];
}

__global__ void k_bn_inplace() {
    size_t idx = (size_t)blockIdx.x * blockDim.x + threadIdx.x;
    if (idx >= (size_t)N_NODES * HDIM) return;
    int j = (int)(idx & 511);
    g_X[idx] = fmaf(g_X[idx], g_bnA[j], g_bnB[j]);
}

__global__ void k_zero_big(int buf) {
    float* p = bufp(buf);
    size_t idx = (size_t)blockIdx.x * blockDim.x + threadIdx.x;
    if (idx < (size_t)N_NODES * HDIM) p[idx] = 0.f;
}

// AGG[dst,:] += X[src,:]   (one block of 128 threads per edge, float4 gather)
__global__ void k_edge_agg(const int* __restrict__ src, const int* __restrict__ dst) {
    int e = blockIdx.x;
    int s = src[e];
    int d = dst[e];
    int j = threadIdx.x;  // 128
    float4 v = ((const float4*)(g_X + (size_t)s * HDIM))[j];
    float* ag = g_AGG + (size_t)d * HDIM + j * 4;
    atomicAdd(ag + 0, v.x);
    atomicAdd(ag + 1, v.y);
    atomicAdd(ag + 2, v.z);
    atomicAdd(ag + 3, v.w);
}

// AGG = (1+eps)*X + AGG
__global__ void k_h0(const float* __restrict__ eps) {
    size_t idx = (size_t)blockIdx.x * blockDim.x + threadIdx.x;
    if (idx >= (size_t)N_NODES * HDIM) return;
    g_AGG[idx] = fmaf(1.f + eps[0], g_X[idx], g_AGG[idx]);
}

// y2 = leaky(Y1 @ w2 + b2) * mask; atomic per-graph max/min.  One warp per node.
__global__ void k_lin2(const float* __restrict__ w, const float* __restrict__ b,
                       const int* __restrict__ batch) {
    int warp = (blockIdx.x * blockDim.x + threadIdx.x) >> 5;
    int lane = threadIdx.x & 31;
    if (warp >= N_NODES) return;
    const float* row = g_Y1 + (size_t)warp * HIDDIM;
    float v = fmaf(row[lane], w[lane], row[lane + 32] * w[lane + 32]);
#pragma unroll
    for (int o = 16; o > 0; o >>= 1) v += __shfl_down_sync(0xffffffffu, v, o);
    if (lane == 0) {
        v = lrelu(v + b[0]) * g_mask[warp];
        g_sB[warp] = v;
        int g = batch[warp];
        atomicMaxFloat(&g_bmax[g], v);
        atomicMinFloat(&g_bmin[g], v);
    }
}

__global__ void k_final(const int* __restrict__ batch, float* __restrict__ out) {
    int i = blockIdx.x * blockDim.x + threadIdx.x;
    if (i >= N_NODES) return;
    int g = batch[i];
    out[i] = (g_sB[i] - g_bmin[g]) / (g_bmax[g] + 1e-6f - g_bmin[g]);
}

// ---------------- host orchestration ----------------
extern "C" void kernel_launch(void* const* d_in, const int* in_sizes, int n_in,
                              void* d_out, int out_size) {
    const float* x    = (const float*)d_in[0];
    const int*   ei   = (const int*)d_in[1];
    const int*   bat  = (const int*)d_in[2];
    const float* c1w1 = (const float*)d_in[3];
    const float* c1b1 = (const float*)d_in[4];
    const float* c1w2 = (const float*)d_in[5];
    const float* c1b2 = (const float*)d_in[6];
    const float* c1g  = (const float*)d_in[7];
    const float* c1b  = (const float*)d_in[8];
    const float* eps1 = (const float*)d_in[9];
    const float* bn1g = (const float*)d_in[10];
    const float* bn1b = (const float*)d_in[11];
    const float* cw1  = (const float*)d_in[12];
    const float* cb1  = (const float*)d_in[13];
    const float* cw2  = (const float*)d_in[14];
    const float* cb2  = (const float*)d_in[15];
    const float* cbng = (const float*)d_in[16];
    const float* cbnb = (const float*)d_in[17];
    const float* ceps = (const float*)d_in[18];
    const float* bnsg = (const float*)d_in[19];
    const float* bnsb = (const float*)d_in[20];
    const float* l1w  = (const float*)d_in[21];
    const float* l1b  = (const float*)d_in[22];
    const float* l2w  = (const float*)d_in[23];
    const float* l2b  = (const float*)d_in[24];
    float* out = (float*)d_out;

    const int* src = ei;
    const int* dst = ei + N_EDGES;

    const int NW  = (N_NODES + 255) / 256;
    const int EW  = (N_EDGES + 255) / 256;
    const size_t NH = (size_t)N_NODES * HDIM;
    const int NHW = (int)((NH + 255) / 256);
    const int BNR = (N_NODES + BN_ROWS - 1) / BN_ROWS;

    dim3 gemmGrid512((HDIM + BN - 1) / BN, (N_NODES + BM - 1) / BM);
    dim3 gemmGrid64 ((HIDDIM + BN - 1) / BN, (N_NODES + BM - 1) / BM);

    // ---- setup: counts, inv_sqrt_n, initial mask + propagate ----
    k_setup<<<1, 64>>>();
    k_count<<<NW, 256>>>(bat);
    k_prep<<<NW, 256>>>(x, bat);
    k_edge_mask<<<EW, 256>>>(src, dst);
    k_mask_update<<<NW, 256>>>();

    // ---- conv1 ----
    k_edge_x<<<EW, 256>>>(src, dst, x);
    k_conv1_h1<<<NHW, 256>>>(x, c1w1, c1b1, eps1);
    k_sgemm<<<gemmGrid512, 256>>>(1, c1w2, c1b2, 2, N_NODES, HDIM, HDIM, 0);   // Hb -> AGG
    k_zstat<<<1, HDIM>>>();
    k_bn_reduce<<<BNR, HDIM>>>(2, N_NODES);
    k_bn_final<<<1, HDIM>>>(c1g, c1b, N_NODES);
    k_apply_conv1<<<NHW, 256>>>();
    k_zstat<<<1, HDIM>>>();
    k_bn_reduce<<<BNR, HDIM>>>(0, N_NODES);
    k_bn_final<<<1, HDIM>>>(bn1g, bn1b, N_NODES);
    k_bn_inplace<<<NHW, 256>>>();

    // ---- 3 mid GIN layers ----
    for (int L = 0; L < 3; L++) {
        const size_t WO = (size_t)L * HDIM * HDIM;
        const size_t BO = (size_t)L * HDIM;
        k_zero_big<<<NHW, 256>>>(2);
        k_edge_agg<<<N_EDGES, 128>>>(src, dst);
        k_h0<<<NHW, 256>>>(ceps + L);
        k_sgemm<<<gemmGrid512, 256>>>(2, cw1 + WO, cb1 + BO, 1, N_NODES, HDIM, HDIM, 0);  // AGG -> Hb
        k_sgemm<<<gemmGrid512, 256>>>(1, cw2 + WO, cb2 + BO, 2, N_NODES, HDIM, HDIM, 0);  // Hb -> AGG
        k_zstat<<<1, HDIM>>>();
        k_bn_reduce<<<BNR, HDIM>>>(2, N_NODES);
        k_bn_final<<<1, HDIM>>>(cbng + BO, cbnb + BO, N_NODES);
        // mask = propagate(mask)
        k_edge_mask<<<EW, 256>>>(src, dst);
        k_mask_update<<<NW, 256>>>();
        // X = (X + leaky(bn(AGG))) * mask * inv
        k_apply_mid<<<NHW, 256>>>();
        k_zstat<<<1, HDIM>>>();
        k_bn_reduce<<<BNR, HDIM>>>(0, N_NODES);
        k_bn_final<<<1, HDIM>>>(bnsg + BO, bnsb + BO, N_NODES);
        k_bn_inplace<<<NHW, 256>>>();
    }

    // ---- head ----
    k_sgemm<<<gemmGrid64, 256>>>(0, l1w, l1b, 3, N_NODES, HDIM, HIDDIM, 1);  // X -> Y1 (leaky*mask)
    k_lin2<<<(N_NODES * 32 + 255) / 256, 256>>>(l2w, l2b, bat);
    k_final<<<NW, 256>>>(bat, out);
}

// round 10
// speedup vs baseline: 1.6154x; 1.6154x over previous
#include <cuda_runtime.h>
#include <cuda_bf16.h>
#include <math.h>
#include <stdint.h>

#define N_NODES 50000
#define N_EDGES 150000
#define HDIM    512
#define HIDDIM  64
#define NGRAPH  64

// ---------------- scratch (device globals; no allocation allowed) ----------------
__device__ float  g_X  [(size_t)N_NODES * HDIM];
__device__ float  g_AGG[(size_t)N_NODES * HDIM];
__device__ float  g_Y1 [(size_t)N_NODES * HIDDIM];
__device__ __nv_bfloat16 g_A1[(size_t)N_NODES * HDIM];  // split set 0 (hi)
__device__ __nv_bfloat16 g_A2[(size_t)N_NODES * HDIM];  // split set 0 (lo)
__device__ __nv_bfloat16 g_C1[(size_t)N_NODES * HDIM];  // split set 1 (hi)
__device__ __nv_bfloat16 g_C2[(size_t)N_NODES * HDIM];  // split set 1 (lo)
__device__ __nv_bfloat16 g_B1[HDIM * HDIM];             // weight split hi, [Nd][K] K-major
__device__ __nv_bfloat16 g_B2[HDIM * HDIM];             // weight split lo
__device__ float  g_mask[N_NODES];
__device__ float  g_inv [N_NODES];
__device__ float  g_sA  [N_NODES];
__device__ float  g_sB  [N_NODES];
__device__ float  g_cnt [NGRAPH];
__device__ float  g_bmax[NGRAPH];
__device__ float  g_bmin[NGRAPH];
__device__ double g_dsum[HDIM];
__device__ double g_dsq [HDIM];
__device__ float  g_bnA [HDIM];
__device__ float  g_bnB [HDIM];

__device__ __forceinline__ float* bufp(int b) {
    switch (b) {
        case 0: return g_X;
        case 2: return g_AGG;
        default: return g_Y1;
    }
}

__device__ __forceinline__ float lrelu(float v) { return v > 0.f ? v : 0.01f * v; }

__device__ __forceinline__ void atomicMaxFloat(float* addr, float v) {
    if (v >= 0.f) atomicMax((int*)addr, __float_as_int(v));
    else          atomicMin((unsigned int*)addr, __float_as_uint(v));
}
__device__ __forceinline__ void atomicMinFloat(float* addr, float v) {
    if (v >= 0.f) atomicMin((int*)addr, __float_as_int(v));
    else          atomicMax((unsigned int*)addr, __float_as_uint(v));
}

__device__ __forceinline__ uint32_t smem_u32(const void* p) {
    uint32_t a;
    asm("{ .reg .u64 t; cvta.to.shared.u64 t, %1; cvt.u32.u64 %0, t; }" : "=r"(a) : "l"(p));
    return a;
}

// ---------------- cp.async helpers (sm_80+ base ISA) ----------------
#define CP_A16(dst, src) \
    asm volatile("cp.async.cg.shared.global [%0], [%1], 16;" :: "r"(dst), "l"(src) : "memory")
#define CP_COMMIT() asm volatile("cp.async.commit_group;" ::: "memory")
#define CP_WAIT1()  asm volatile("cp.async.wait_group 1;" ::: "memory")
#define CP_WAIT0()  asm volatile("cp.async.wait_group 0;" ::: "memory")

// ---------------- mma.sync bf16 (sm_80+ base ISA) ----------------
__device__ __forceinline__ void mma_bf16(float* c, const uint32_t* a, const uint32_t* b) {
    asm volatile(
        "mma.sync.aligned.m16n8k16.row.col.f32.bf16.bf16.f32 "
        "{%0,%1,%2,%3}, {%4,%5,%6,%7}, {%8,%9}, {%0,%1,%2,%3};"
        : "+f"(c[0]), "+f"(c[1]), "+f"(c[2]), "+f"(c[3])
        : "r"(a[0]), "r"(a[1]), "r"(a[2]), "r"(a[3]), "r"(b[0]), "r"(b[1]));
}

// ---------------- split helpers ----------------
__device__ __forceinline__ void split_store(__nv_bfloat16* o1, __nv_bfloat16* o2, size_t idx, float v) {
    __nv_bfloat16 h = __float2bfloat16(v);
    o1[idx] = h;
    o2[idx] = __float2bfloat16(v - __bfloat162float(h));
}

// ---------------- small setup kernels ----------------
__global__ void k_setup() {
    int t = threadIdx.x;
    if (t < NGRAPH) {
        g_cnt[t]  = 0.f;
        g_bmax[t] = __int_as_float(0xff800000);
        g_bmin[t] = __int_as_float(0x7f800000);
    }
}
__global__ void k_count(const int* __restrict__ batch) {
    int i = blockIdx.x * blockDim.x + threadIdx.x;
    if (i < N_NODES) atomicAdd(&g_cnt[batch[i]], 1.0f);
}
__global__ void k_prep(const float* __restrict__ x, const int* __restrict__ batch) {
    int i = blockIdx.x * blockDim.x + threadIdx.x;
    if (i < N_NODES) {
        g_inv[i]  = rsqrtf(g_cnt[batch[i]]);
        g_mask[i] = (fabsf(x[i]) > 0.f) ? 1.f : 0.f;
        g_sA[i] = 0.f;
        g_sB[i] = 0.f;
    }
}
__global__ void k_edge_mask(const int* __restrict__ src, const int* __restrict__ dst) {
    int e = blockIdx.x * blockDim.x + threadIdx.x;
    if (e < N_EDGES) atomicAdd(&g_sA[dst[e]], g_mask[src[e]]);
}
__global__ void k_mask_update() {
    int i = blockIdx.x * blockDim.x + threadIdx.x;
    if (i < N_NODES) {
        g_mask[i] = (g_mask[i] + g_sA[i] > 0.f) ? 1.f : 0.f;
        g_sA[i] = 0.f;
    }
}
__global__ void k_edge_x(const int* __restrict__ src, const int* __restrict__ dst,
                         const float* __restrict__ x) {
    int e = blockIdx.x * blockDim.x + threadIdx.x;
    if (e < N_EDGES) atomicAdd(&g_sB[dst[e]], x[src[e]]);
}

// h1 = relu(((1+eps)*x + agg) * w1[j] + b1[j]) -> split set 0
__global__ void k_conv1_h1s(const float* __restrict__ x, const float* __restrict__ w1,
                            const float* __restrict__ b1, const float* __restrict__ eps) {
    size_t idx = (size_t)blockIdx.x * blockDim.x + threadIdx.x;
    if (idx >= (size_t)N_NODES * HDIM) return;
    int i = (int)(idx >> 9);
    int j = (int)(idx & 511);
    float h0 = (1.f + eps[0]) * x[i] + g_sB[i];
    float v = fmaxf(fmaf(h0, w1[j], b1[j]), 0.f);
    split_store(g_A1, g_A2, idx, v);
}

// weight split + transpose: W [K, Nd] fp32 -> g_B1/g_B2 [Nd][512] bf16 (K-major)
__global__ void k_splitW(const float* __restrict__ W, int K, int Nd) {
    int idx = blockIdx.x * blockDim.x + threadIdx.x;
    if (idx >= K * Nd) return;
    int k = idx / Nd, n = idx % Nd;
    float v = W[idx];
    __nv_bfloat16 h = __float2bfloat16(v);
    g_B1[(size_t)n * HDIM + k] = h;
    g_B2[(size_t)n * HDIM + k] = __float2bfloat16(v - __bfloat162float(h));
}

// ---------------- mma.sync GEMM: C = epi(A @ W^T + bias) ----------------
// A (split bf16 hi/lo, [M,512]) selected by inSel; W pre-split/transposed in g_B1/g_B2.
// mode 0: relu -> Cbuf fp32; mode 1: leaky*mask -> Cbuf fp32; mode 2: relu -> split set 1.
#define GSTRIDE 40                       // smem row stride in bf16 elements (80B = 20 banks)
#define GTILE_B (128 * GSTRIDE * 2)      // 10240 bytes per tile
#define GBUF_SZ (4 * GTILE_B)            // A1,A2,B1,B2
#define GSMEM_T (2 * GBUF_SZ)            // double buffer = 81920

__device__ __forceinline__ void load_chunk_async(
        char* smem, int b, const __nv_bfloat16* __restrict__ A1,
        const __nv_bfloat16* __restrict__ A2,
        int row0, int col0, int kt, int M, int bN) {
    int tid = threadIdx.x;
    int row = tid >> 1;        // 0..127
    int h   = tid & 1;         // covers 32B each (chunk is 64B/row)
    uint32_t d = smem_u32(smem) + (uint32_t)b * GBUF_SZ + (uint32_t)row * (GSTRIDE * 2) + h * 32;
    int ar = min(row0 + row, M - 1);
    const char* sa1 = (const char*)(A1 + (size_t)ar * HDIM + kt) + h * 32;
    const char* sa2 = (const char*)(A2 + (size_t)ar * HDIM + kt) + h * 32;
    int nr = col0 + min(row, bN - 1);
    const char* sb1 = (const char*)(g_B1 + (size_t)nr * HDIM + kt) + h * 32;
    const char* sb2 = (const char*)(g_B2 + (size_t)nr * HDIM + kt) + h * 32;
    CP_A16(d + 0 * GTILE_B,      sa1);
    CP_A16(d + 0 * GTILE_B + 16, sa1 + 16);
    CP_A16(d + 1 * GTILE_B,      sa2);
    CP_A16(d + 1 * GTILE_B + 16, sa2 + 16);
    CP_A16(d + 2 * GTILE_B,      sb1);
    CP_A16(d + 2 * GTILE_B + 16, sb1 + 16);
    CP_A16(d + 3 * GTILE_B,      sb2);
    CP_A16(d + 3 * GTILE_B + 16, sb2 + 16);
}

__global__ __launch_bounds__(256, 1)
void k_mmagemm(const float* __restrict__ bias, int inSel, int Cbuf,
               int M, int Nd, int bN, int mode) {
    extern __shared__ char smem[];
    const __nv_bfloat16* A1 = inSel ? g_C1 : g_A1;
    const __nv_bfloat16* A2 = inSel ? g_C2 : g_A2;

    int tid   = threadIdx.x;
    int wid   = tid >> 5;
    int lane  = tid & 31;
    int group = lane >> 2;     // 0..7
    int t4    = lane & 3;      // 0..3
    int row0  = blockIdx.y * 128;
    int col0  = blockIdx.x * 128;
    int wm    = (wid & 3) * 32;    // warp row offset
    int wn    = (wid >> 2) * 64;   // warp col offset

    float acc[2][8][4];
#pragma unroll
    for (int t = 0; t < 2; t++)
#pragma unroll
        for (int j = 0; j < 8; j++)
#pragma unroll
            for (int r = 0; r < 4; r++) acc[t][j][r] = 0.f;

    load_chunk_async(smem, 0, A1, A2, row0, col0, 0, M, bN);
    CP_COMMIT();

    for (int c = 0; c < 16; c++) {
        if (c < 15) {
            load_chunk_async(smem, (c + 1) & 1, A1, A2, row0, col0, (c + 1) * 32, M, bN);
            CP_COMMIT();
            CP_WAIT1();
        } else {
            CP_WAIT0();
        }
        __syncthreads();

        const uint16_t* As1 = (const uint16_t*)(smem + (c & 1) * GBUF_SZ);
        const uint16_t* As2 = As1 + 128 * GSTRIDE;
        const uint16_t* Bs1 = As1 + 2 * 128 * GSTRIDE;
        const uint16_t* Bs2 = As1 + 3 * 128 * GSTRIDE;

#pragma unroll
        for (int kk = 0; kk < 32; kk += 16) {
            uint32_t a1f[2][4], a2f[2][4], b1f[8][2], b2f[8][2];
#pragma unroll
            for (int t = 0; t < 2; t++) {
                int r = (wm + t * 16 + group) * GSTRIDE + kk + t4 * 2;
                a1f[t][0] = *(const uint32_t*)(As1 + r);
                a1f[t][1] = *(const uint32_t*)(As1 + r + 8 * GSTRIDE);
                a1f[t][2] = *(const uint32_t*)(As1 + r + 8);
                a1f[t][3] = *(const uint32_t*)(As1 + r + 8 * GSTRIDE + 8);
                a2f[t][0] = *(const uint32_t*)(As2 + r);
                a2f[t][1] = *(const uint32_t*)(As2 + r + 8 * GSTRIDE);
                a2f[t][2] = *(const uint32_t*)(As2 + r + 8);
                a2f[t][3] = *(const uint32_t*)(As2 + r + 8 * GSTRIDE + 8);
            }
#pragma unroll
            for (int j = 0; j < 8; j++) {
                int r = (wn + j * 8 + group) * GSTRIDE + kk + t4 * 2;
                b1f[j][0] = *(const uint32_t*)(Bs1 + r);
                b1f[j][1] = *(const uint32_t*)(Bs1 + r + 8);
                b2f[j][0] = *(const uint32_t*)(Bs2 + r);
                b2f[j][1] = *(const uint32_t*)(Bs2 + r + 8);
            }
#pragma unroll
            for (int t = 0; t < 2; t++)
#pragma unroll
                for (int j = 0; j < 8; j++) {
                    mma_bf16(acc[t][j], a1f[t], b1f[j]);
                    mma_bf16(acc[t][j], a2f[t], b1f[j]);
                    mma_bf16(acc[t][j], a1f[t], b2f[j]);
                }
        }
        __syncthreads();
    }

    // ---- epilogue ----
    float* C = bufp(Cbuf);
#pragma unroll
    for (int t = 0; t < 2; t++) {
        int rlo = row0 + wm + t * 16 + group;
        int rhi = rlo + 8;
#pragma unroll
        for (int j = 0; j < 8; j++) {
            int col = col0 + wn + j * 8 + t4 * 2;
            if (col >= Nd) continue;
            float b0 = bias[col], b1v = bias[col + 1];
            float v00 = acc[t][j][0] + b0, v01 = acc[t][j][1] + b1v;
            float v10 = acc[t][j][2] + b0, v11 = acc[t][j][3] + b1v;
            if (mode == 2) {
                if (rlo < M) {
                    float u0 = fmaxf(v00, 0.f), u1 = fmaxf(v01, 0.f);
                    __nv_bfloat16 h0 = __float2bfloat16(u0), h1 = __float2bfloat16(u1);
                    size_t o = (size_t)rlo * HDIM + col;
                    *(__nv_bfloat162*)(g_C1 + o) = __halves2bfloat162(h0, h1);
                    *(__nv_bfloat162*)(g_C2 + o) = __halves2bfloat162(
                        __float2bfloat16(u0 - __bfloat162float(h0)),
                        __float2bfloat16(u1 - __bfloat162float(h1)));
                }
                if (rhi < M) {
                    float u0 = fmaxf(v10, 0.f), u1 = fmaxf(v11, 0.f);
                    __nv_bfloat16 h0 = __float2bfloat16(u0), h1 = __float2bfloat16(u1);
                    size_t o = (size_t)rhi * HDIM + col;
                    *(__nv_bfloat162*)(g_C1 + o) = __halves2bfloat162(h0, h1);
                    *(__nv_bfloat162*)(g_C2 + o) = __halves2bfloat162(
                        __float2bfloat16(u0 - __bfloat162float(h0)),
                        __float2bfloat16(u1 - __bfloat162float(h1)));
                }
            } else if (mode == 0) {
                if (rlo < M) *(float2*)(C + (size_t)rlo * Nd + col) =
                    make_float2(fmaxf(v00, 0.f), fmaxf(v01, 0.f));
                if (rhi < M) *(float2*)(C + (size_t)rhi * Nd + col) =
                    make_float2(fmaxf(v10, 0.f), fmaxf(v11, 0.f));
            } else {
                if (rlo < M) {
                    float mi = g_mask[rlo];
                    *(float2*)(C + (size_t)rlo * Nd + col) =
                        make_float2(lrelu(v00) * mi, lrelu(v01) * mi);
                }
                if (rhi < M) {
                    float mi = g_mask[rhi];
                    *(float2*)(C + (size_t)rhi * Nd + col) =
                        make_float2(lrelu(v10) * mi, lrelu(v11) * mi);
                }
            }
        }
    }
}

// ---------------- BN helpers ----------------
__global__ void k_zstat() {
    int t = threadIdx.x;
    g_dsum[t] = 0.0;
    g_dsq[t]  = 0.0;
}

#define BN_ROWS 256
__global__ void k_bn_reduce(int buf, int M) {
    const float* X = bufp(buf);
    int col = threadIdx.x;
    int r0  = blockIdx.x * BN_ROWS;
    int r1  = min(r0 + BN_ROWS, M);
    float s = 0.f, q = 0.f;
    for (int r = r0; r < r1; r++) {
        float v = X[(size_t)r * HDIM + col];
        s += v;
        q = fmaf(v, v, q);
    }
    atomicAdd(&g_dsum[col], (double)s);
    atomicAdd(&g_dsq[col], (double)q);
}

__global__ void k_bn_final(const float* __restrict__ gam, const float* __restrict__ bet, int M) {
    int j = threadIdx.x;
    double mu  = g_dsum[j] / (double)M;
    double var = g_dsq[j] / (double)M - mu * mu;
    float  rs  = rsqrtf(fmaxf((float)var, 0.f) + 1e-5f);
    float  a   = gam[j] * rs;
    g_bnA[j] = a;
    g_bnB[j] = bet[j] - a * (float)mu;
}

__global__ void k_apply_conv1() {
    size_t idx = (size_t)blockIdx.x * blockDim.x + threadIdx.x;
    if (idx >= (size_t)N_NODES * HDIM) return;
    int i = (int)(idx >> 9);
    int j = (int)(idx & 511);
    float v = lrelu(fmaf(g_AGG[idx], g_bnA[j], g_bnB[j]));
    g_X[idx] = v * g_mask[i] * g_inv[i];
}

__global__ void k_apply_mid() {
    size_t idx = (size_t)blockIdx.x * blockDim.x + threadIdx.x;
    if (idx >= (size_t)N_NODES * HDIM) return;
    int i = (int)(idx >> 9);
    int j = (int)(idx & 511);
    float t = lrelu(fmaf(g_AGG[idx], g_bnA[j], g_bnB[j]));
    g_X[idx] = (g_X[idx] + t) * g_mask[i] * g_inv[i];
}

// bn in place; optionally emit split set 0 (feeds lin1)
__global__ void k_bn_inplace(int emit) {
    size_t idx = (size_t)blockIdx.x * blockDim.x + threadIdx.x;
    if (idx >= (size_t)N_NODES * HDIM) return;
    int j = (int)(idx & 511);
    float v = fmaf(g_X[idx], g_bnA[j], g_bnB[j]);
    g_X[idx] = v;
    if (emit) split_store(g_A1, g_A2, idx, v);
}

__global__ void k_zero_big() {
    size_t idx = (size_t)blockIdx.x * blockDim.x + threadIdx.x;
    if (idx < (size_t)N_NODES * HDIM) g_AGG[idx] = 0.f;
}

__global__ void k_edge_agg(const int* __restrict__ src, const int* __restrict__ dst) {
    int e = blockIdx.x;
    int s = src[e];
    int d = dst[e];
    int j = threadIdx.x;
    float4 v = ((const float4*)(g_X + (size_t)s * HDIM))[j];
    float* ag = g_AGG + (size_t)d * HDIM + j * 4;
    atomicAdd(ag + 0, v.x);
    atomicAdd(ag + 1, v.y);
    atomicAdd(ag + 2, v.z);
    atomicAdd(ag + 3, v.w);
}

// h0 = (1+eps)*X + AGG  -> split set 0 (no relu; relu happens in GEMM epilogue)
__global__ void k_h0s(const float* __restrict__ eps) {
    size_t idx = (size_t)blockIdx.x * blockDim.x + threadIdx.x;
    if (idx >= (size_t)N_NODES * HDIM) return;
    float v = fmaf(1.f + eps[0], g_X[idx], g_AGG[idx]);
    split_store(g_A1, g_A2, idx, v);
}

__global__ void k_lin2(const float* __restrict__ w, const float* __restrict__ b,
                       const int* __restrict__ batch) {
    int warp = (blockIdx.x * blockDim.x + threadIdx.x) >> 5;
    int lane = threadIdx.x & 31;
    if (warp >= N_NODES) return;
    const float* row = g_Y1 + (size_t)warp * HIDDIM;
    float v = fmaf(row[lane], w[lane], row[lane + 32] * w[lane + 32]);
#pragma unroll
    for (int o = 16; o > 0; o >>= 1) v += __shfl_down_sync(0xffffffffu, v, o);
    if (lane == 0) {
        v = lrelu(v + b[0]) * g_mask[warp];
        g_sB[warp] = v;
        int g = batch[warp];
        atomicMaxFloat(&g_bmax[g], v);
        atomicMinFloat(&g_bmin[g], v);
    }
}

__global__ void k_final(const int* __restrict__ batch, float* __restrict__ out) {
    int i = blockIdx.x * blockDim.x + threadIdx.x;
    if (i >= N_NODES) return;
    int g = batch[i];
    out[i] = (g_sB[i] - g_bmin[g]) / (g_bmax[g] + 1e-6f - g_bmin[g]);
}

// ---------------- host orchestration ----------------
extern "C" void kernel_launch(void* const* d_in, const int* in_sizes, int n_in,
                              void* d_out, int out_size) {
    const float* x    = (const float*)d_in[0];
    const int*   ei   = (const int*)d_in[1];
    const int*   bat  = (const int*)d_in[2];
    const float* c1w1 = (const float*)d_in[3];
    const float* c1b1 = (const float*)d_in[4];
    const float* c1w2 = (const float*)d_in[5];
    const float* c1b2 = (const float*)d_in[6];
    const float* c1g  = (const float*)d_in[7];
    const float* c1b  = (const float*)d_in[8];
    const float* eps1 = (const float*)d_in[9];
    const float* bn1g = (const float*)d_in[10];
    const float* bn1b = (const float*)d_in[11];
    const float* cw1  = (const float*)d_in[12];
    const float* cb1  = (const float*)d_in[13];
    const float* cw2  = (const float*)d_in[14];
    const float* cb2  = (const float*)d_in[15];
    const float* cbng = (const float*)d_in[16];
    const float* cbnb = (const float*)d_in[17];
    const float* ceps = (const float*)d_in[18];
    const float* bnsg = (const float*)d_in[19];
    const float* bnsb = (const float*)d_in[20];
    const float* l1w  = (const float*)d_in[21];
    const float* l1b  = (const float*)d_in[22];
    const float* l2w  = (const float*)d_in[23];
    const float* l2b  = (const float*)d_in[24];
    float* out = (float*)d_out;

    const int* src = ei;
    const int* dst = ei + N_EDGES;

    cudaFuncSetAttribute(k_mmagemm, cudaFuncAttributeMaxDynamicSharedMemorySize, GSMEM_T);

    const int NW  = (N_NODES + 255) / 256;
    const int EW  = (N_EDGES + 255) / 256;
    const size_t NH = (size_t)N_NODES * HDIM;
    const int NHW = (int)((NH + 255) / 256);
    const int BNR = (N_NODES + BN_ROWS - 1) / BN_ROWS;
    const int WW  = (HDIM * HDIM + 255) / 256;
    const int WL  = (HDIM * HIDDIM + 255) / 256;

    dim3 gg512(4, (N_NODES + 127) / 128);
    dim3 gg64 (1, (N_NODES + 127) / 128);

    // ---- setup ----
    k_setup<<<1, 64>>>();
    k_count<<<NW, 256>>>(bat);
    k_prep<<<NW, 256>>>(x, bat);
    k_edge_mask<<<EW, 256>>>(src, dst);
    k_mask_update<<<NW, 256>>>();

    // ---- conv1 ----
    k_edge_x<<<EW, 256>>>(src, dst, x);
    k_conv1_h1s<<<NHW, 256>>>(x, c1w1, c1b1, eps1);            // -> split set 0
    k_splitW<<<WW, 256>>>(c1w2, HDIM, HDIM);
    k_mmagemm<<<gg512, 256, GSMEM_T>>>(c1b2, 0, 2, N_NODES, HDIM, 128, 0);  // set0 -> AGG (relu)
    k_zstat<<<1, HDIM>>>();
    k_bn_reduce<<<BNR, HDIM>>>(2, N_NODES);
    k_bn_final<<<1, HDIM>>>(c1g, c1b, N_NODES);
    k_apply_conv1<<<NHW, 256>>>();
    k_zstat<<<1, HDIM>>>();
    k_bn_reduce<<<BNR, HDIM>>>(0, N_NODES);
    k_bn_final<<<1, HDIM>>>(bn1g, bn1b, N_NODES);
    k_bn_inplace<<<NHW, 256>>>(0);

    // ---- 3 mid GIN layers ----
    for (int L = 0; L < 3; L++) {
        const size_t WO = (size_t)L * HDIM * HDIM;
        const size_t BO = (size_t)L * HDIM;
        k_zero_big<<<NHW, 256>>>();
        k_edge_agg<<<N_EDGES, 128>>>(src, dst);
        k_h0s<<<NHW, 256>>>(ceps + L);                          // -> split set 0
        k_splitW<<<WW, 256>>>(cw1 + WO, HDIM, HDIM);
        k_mmagemm<<<gg512, 256, GSMEM_T>>>(cb1 + BO, 0, 0, N_NODES, HDIM, 128, 2);  // set0 -> set1 (relu, split)
        k_splitW<<<WW, 256>>>(cw2 + WO, HDIM, HDIM);
        k_mmagemm<<<gg512, 256, GSMEM_T>>>(cb2 + BO, 1, 2, N_NODES, HDIM, 128, 0);  // set1 -> AGG (relu)
        k_zstat<<<1, HDIM>>>();
        k_bn_reduce<<<BNR, HDIM>>>(2, N_NODES);
        k_bn_final<<<1, HDIM>>>(cbng + BO, cbnb + BO, N_NODES);
        k_edge_mask<<<EW, 256>>>(src, dst);
        k_mask_update<<<NW, 256>>>();
        k_apply_mid<<<NHW, 256>>>();
        k_zstat<<<1, HDIM>>>();
        k_bn_reduce<<<BNR, HDIM>>>(0, N_NODES);
        k_bn_final<<<1, HDIM>>>(bnsg + BO, bnsb + BO, N_NODES);
        k_bn_inplace<<<NHW, 256>>>(L == 2 ? 1 : 0);             // last one emits split for lin1
    }

    // ---- head ----
    k_splitW<<<WL, 256>>>(l1w, HDIM, HIDDIM);
    k_mmagemm<<<gg64, 256, GSMEM_T>>>(l1b, 0, 3, N_NODES, HIDDIM, 64, 1);   // set0 -> Y1 (leaky*mask)
    k_lin2<<<(N_NODES * 32 + 255) / 256, 256>>>(l2w, l2b, bat);
    k_final<<<NW, 256>>>(bat, out);
}